// round 1
// baseline (speedup 1.0000x reference)
#include <cuda_runtime.h>
#include <stdint.h>

// LayoutBBox: inputs (B, 12, 64) f32 -> out (B, 8, 128, 128) f32
// out[b,c,h,w] = max_n xy_max[b,n,h,w] * cls[b,n,c]
// xy_max = max( lx(w)*gx(h), ly(h)*gy(w) )  (separable box-outline render)

constexpr int Wd   = 128;
constexpr int Hd   = 128;
constexpr int NUMB = 64;
constexpr int NCLS = 8;
constexpr int NDIM = 4;
constexpr int INCH = NDIM + NCLS;   // 12
constexpr int ROWS = 8;             // rows per block (blockDim = 128 x 8)

__global__ __launch_bounds__(1024, 2)
void layout_bbox_kernel(const float* __restrict__ in, float* __restrict__ out)
{
    __shared__ float4 sparams[NUMB];      // x1, x2, y1, y2 per box
    __shared__ float4 scls[NUMB * 2];     // 8 class probs per box as 2x float4
    extern __shared__ float2 sdyn[];
    float2* swtab = sdyn;                 // [NUMB][Wd]  : (lx, gy) per (n, w)
    float2* shtab = sdyn + NUMB * Wd;     // [NUMB][ROWS]: (gx, ly) per (n, row)

    const int tx  = threadIdx.x;          // w   in [0,128)
    const int ty  = threadIdx.y;          // row in [0,8)
    const int tid = ty * Wd + tx;
    const int b   = blockIdx.y;
    const int h   = blockIdx.x * ROWS + ty;
    const float hf = (float)h;

    // ---- load box params + class probs (threads 0..63, one box each) ----
    if (tid < NUMB) {
        const float* base = in + (size_t)b * INCH * NUMB + tid;
        float xc = base[0 * NUMB] * 128.0f;
        float yc = base[1 * NUMB] * 128.0f;
        float bw = base[2 * NUMB] * 128.0f;
        float bh = base[3 * NUMB] * 128.0f;
        sparams[tid] = make_float4(xc - 0.5f * bw, xc + 0.5f * bw,
                                   yc - 0.5f * bh, yc + 0.5f * bh);
        scls[tid * 2 + 0] = make_float4(base[4 * NUMB], base[5 * NUMB],
                                        base[6 * NUMB], base[7 * NUMB]);
        scls[tid * 2 + 1] = make_float4(base[8 * NUMB], base[9 * NUMB],
                                        base[10 * NUMB], base[11 * NUMB]);
    }
    __syncthreads();

    // ---- build per-box 1-D profile tables ----
    #pragma unroll
    for (int i = tid; i < NUMB * Wd; i += Wd * ROWS) {
        int n = i >> 7, wv = i & 127;
        float wf = (float)wv;
        float4 p = sparams[n];
        float lx = fmaxf(0.0f, fmaxf(1.0f - fabsf(wf - p.x),
                                     1.0f - fabsf(p.y - wf)));
        float gy = __saturatef(wf - p.x) * __saturatef(p.y - wf);
        swtab[i] = make_float2(lx, gy);
    }
    if (tid < NUMB * ROWS) {
        int n = tid >> 3, r = tid & 7;
        float rf = (float)(blockIdx.x * ROWS + r);
        float4 p = sparams[n];
        float gx = __saturatef(rf - p.z) * __saturatef(p.w - rf);
        float ly = fmaxf(0.0f, fmaxf(1.0f - fabsf(rf - p.z),
                                     1.0f - fabsf(p.w - rf)));
        shtab[tid] = make_float2(gx, ly);
    }
    __syncthreads();

    // ---- per-warp active-box mask (conservative superset) ----
    // Warp = 32 consecutive w at fixed (h). Box contributes at some lane iff:
    //  vertical edge:   x1 or x2 within (wlo-1, whi+1)  AND  y1 < h < y2
    //  horizontal edge: |h-y1|<1 or |h-y2|<1  AND  (x1,x2) overlaps [wlo,whi]
    const float wlo = (float)(tx & ~31);
    const float whi = wlo + 31.0f;
    const int   ln  = tx & 31;
    unsigned msk[2];
    #pragma unroll
    for (int half = 0; half < 2; half++) {
        int n = ln + half * 32;
        float4 p = sparams[n];
        bool gatey = (p.z < hf) && (hf < p.w);
        bool av = gatey && ((p.x > wlo - 1.0f && p.x < whi + 1.0f) ||
                            (p.y > wlo - 1.0f && p.y < whi + 1.0f));
        bool ah = (fabsf(hf - p.z) < 1.0f || fabsf(hf - p.w) < 1.0f) &&
                  (p.x < whi) && (p.y > wlo);
        msk[half] = __ballot_sync(0xFFFFFFFFu, av || ah);
    }

    // ---- iterate active boxes only; 8 class accumulators in registers ----
    float a0 = 0.f, a1 = 0.f, a2 = 0.f, a3 = 0.f;
    float a4 = 0.f, a5 = 0.f, a6 = 0.f, a7 = 0.f;

    #pragma unroll
    for (int half = 0; half < 2; half++) {
        unsigned mm = msk[half];
        int nbase = half * 32;
        while (mm) {
            int n = (__ffs(mm) - 1) + nbase;
            mm &= mm - 1;
            float2 wv = swtab[((n & 63) << 7) + tx];   // (lx, gy), conflict-free
            float2 hv = shtab[((n & 63) << 3) + ty];   // (gx, ly), broadcast
            float xy = fmaxf(wv.x * hv.x, hv.y * wv.y);
            float4 c0 = scls[(n & 63) * 2 + 0];        // broadcast
            float4 c1 = scls[(n & 63) * 2 + 1];
            a0 = fmaxf(a0, xy * c0.x);  a1 = fmaxf(a1, xy * c0.y);
            a2 = fmaxf(a2, xy * c0.z);  a3 = fmaxf(a3, xy * c0.w);
            a4 = fmaxf(a4, xy * c1.x);  a5 = fmaxf(a5, xy * c1.y);
            a6 = fmaxf(a6, xy * c1.z);  a7 = fmaxf(a7, xy * c1.w);
        }
    }

    // ---- write out[b, c, h, w]; coalesced 128B per warp per class ----
    float* o = out + (((size_t)b * NCLS) * Hd + h) * Wd + tx;
    const int cs = Hd * Wd;   // 16384
    o[0 * cs] = a0;  o[1 * cs] = a1;  o[2 * cs] = a2;  o[3 * cs] = a3;
    o[4 * cs] = a4;  o[5 * cs] = a5;  o[6 * cs] = a6;  o[7 * cs] = a7;
}

extern "C" void kernel_launch(void* const* d_in, const int* in_sizes, int n_in,
                              void* d_out, int out_size)
{
    const float* in = (const float*)d_in[0];
    float* out = (float*)d_out;
    int B = in_sizes[0] / (INCH * NUMB);   // 16 for this problem

    size_t dynsmem = (size_t)(NUMB * Wd + NUMB * ROWS) * sizeof(float2); // 69632 B
    static bool attr_set = false;
    // cudaFuncSetAttribute is not a stream op; safe (and idempotent) under capture.
    cudaFuncSetAttribute(layout_bbox_kernel,
                         cudaFuncAttributeMaxDynamicSharedMemorySize,
                         (int)dynsmem);
    (void)attr_set;

    dim3 grid(Hd / ROWS, B);   // (16, 16)
    dim3 block(Wd, ROWS);      // 128 x 8 = 1024 threads
    layout_bbox_kernel<<<grid, block, dynsmem>>>(in, out);
}

// round 3
// speedup vs baseline: 1.2571x; 1.2571x over previous
#include <cuda_runtime.h>
#include <stdint.h>

// LayoutBBox: in (B,12,64) f32 -> out (B,8,128,128) f32
// out[b,c,h,w] = max_n xy[n,h,w] * cls[n,c],  xy = max(lx(w)*gx(h), ly(h)*gy(w))
// Exact per-pixel active-box bitmask + packed f32x2 multiplies, scalar max.

constexpr int Wd   = 128;
constexpr int Hd   = 128;
constexpr int NUMB = 64;
constexpr int NCLS = 8;
constexpr int INCH = 12;
constexpr int RPB  = 16;   // rows per block (two passes of blockDim.y = 8)
constexpr int TY   = 8;

using u64 = unsigned long long;

__device__ __forceinline__ u64 pk(float lo, float hi) {
    u64 r; asm("mov.b64 %0,{%1,%2};" : "=l"(r) : "f"(lo), "f"(hi)); return r;
}
__device__ __forceinline__ void upk(float& lo, float& hi, u64 v) {
    asm("mov.b64 {%0,%1},%2;" : "=f"(lo), "=f"(hi) : "l"(v));
}
__device__ __forceinline__ u64 pmul(u64 a, u64 b) {
    u64 r; asm("mul.rn.f32x2 %0,%1,%2;" : "=l"(r) : "l"(a), "l"(b)); return r;
}

__global__ __launch_bounds__(1024, 1)
void layout_bbox_kernel(const float* __restrict__ in, float* __restrict__ out)
{
    __shared__ float4     sparams[NUMB];       // x1,x2,y1,y2
    __shared__ ulonglong2 sclsA[NUMB];         // packed (c0,c1),(c2,c3)
    __shared__ ulonglong2 sclsB[NUMB];         // packed (c4,c5),(c6,c7)
    extern __shared__ u64 dyn[];
    u64* swtab = dyn;                          // [NUMB][Wd] packed (lx, gy)
    u64* shtab = swtab + NUMB * Wd;            // [RPB][NUMB] packed (gx, ly)
    u64* Mlx   = shtab + RPB * NUMB;           // [Wd]  bit n: lx(w)>0
    u64* Mgw   = Mlx + Wd;                     // [Wd]  bit n: gy(w)>0
    u64* Mgh   = Mgw + Wd;                     // [RPB] bit n: gx(h)>0
    u64* Mly   = Mgh + RPB;                    // [RPB] bit n: ly(h)>0

    const int tx  = threadIdx.x;               // w
    const int ty  = threadIdx.y;
    const int tid = ty * Wd + tx;
    const int b   = blockIdx.y;
    const int hbase = blockIdx.x * RPB;

    // ---- box params + class probs ----
    if (tid < NUMB) {
        const float* base = in + (size_t)b * INCH * NUMB + tid;
        float xc = base[0 * NUMB] * 128.0f;
        float yc = base[1 * NUMB] * 128.0f;
        float bw = base[2 * NUMB] * 128.0f;
        float bh = base[3 * NUMB] * 128.0f;
        sparams[tid] = make_float4(xc - 0.5f * bw, xc + 0.5f * bw,
                                   yc - 0.5f * bh, yc + 0.5f * bh);
        ulonglong2 ca, cb;
        ca.x = pk(base[4 * NUMB],  base[5 * NUMB]);
        ca.y = pk(base[6 * NUMB],  base[7 * NUMB]);
        cb.x = pk(base[8 * NUMB],  base[9 * NUMB]);
        cb.y = pk(base[10 * NUMB], base[11 * NUMB]);
        sclsA[tid] = ca;
        sclsB[tid] = cb;
    }
    __syncthreads();

    // ---- per-(n,w) profile table: packed (lx, gy) ----
    #pragma unroll
    for (int i = tid; i < NUMB * Wd; i += Wd * TY) {
        int n = i >> 7, wv = i & 127;
        float wf = (float)wv;
        float4 p = sparams[n];
        float lx = fmaxf(0.0f, fmaxf(1.0f - fabsf(wf - p.x),
                                     1.0f - fabsf(p.y - wf)));
        float gy = __saturatef(wf - p.x) * __saturatef(p.y - wf);
        swtab[i] = pk(lx, gy);
    }
    // ---- per-(row,n) profile table: packed (gx, ly) ----
    {
        int r = tid >> 6, n = tid & 63;        // tid covers RPB*NUMB = 1024
        float rf = (float)(hbase + r);
        float4 p = sparams[n];
        float gx = __saturatef(rf - p.z) * __saturatef(p.w - rf);
        float ly = fmaxf(0.0f, fmaxf(1.0f - fabsf(rf - p.z),
                                     1.0f - fabsf(p.w - rf)));
        shtab[(r << 6) + n] = pk(gx, ly);
    }
    // ---- column masks: byte-per-thread build (little-endian bytes of u64) ----
    {
        int w = tid >> 3, j = tid & 7;
        float wf = (float)w;
        unsigned blx = 0, bgw = 0;
        #pragma unroll
        for (int k = 0; k < 8; k++) {
            float4 p = sparams[8 * j + k];
            if (fabsf(wf - p.x) < 1.0f || fabsf(p.y - wf) < 1.0f) blx |= 1u << k;
            if (wf > p.x && wf < p.y)                             bgw |= 1u << k;
        }
        ((unsigned char*)Mlx)[w * 8 + j] = (unsigned char)blx;
        ((unsigned char*)Mgw)[w * 8 + j] = (unsigned char)bgw;
    }
    // ---- row masks ----
    if (tid < RPB * 8) {
        int r = tid >> 3, j = tid & 7;
        float rf = (float)(hbase + r);
        unsigned bgh = 0, bly = 0;
        #pragma unroll
        for (int k = 0; k < 8; k++) {
            float4 p = sparams[8 * j + k];
            if (rf > p.z && rf < p.w)                             bgh |= 1u << k;
            if (fabsf(rf - p.z) < 1.0f || fabsf(p.w - rf) < 1.0f) bly |= 1u << k;
        }
        ((unsigned char*)Mgh)[r * 8 + j] = (unsigned char)bgh;
        ((unsigned char*)Mly)[r * 8 + j] = (unsigned char)bly;
    }
    __syncthreads();

    const u64 mlx = Mlx[tx];
    const u64 mgw = Mgw[tx];

    #pragma unroll
    for (int pass = 0; pass < 2; pass++) {
        const int r = ty + pass * TY;
        const int h = hbase + r;

        // exact nonzero-box set for this pixel
        u64 m = (mlx & Mgh[r]) | (mgw & Mly[r]);

        float a0 = 0.f, a1 = 0.f, a2 = 0.f, a3 = 0.f;
        float a4 = 0.f, a5 = 0.f, a6 = 0.f, a7 = 0.f;
        while (m) {                              // divergent per-lane loop
            int n = __ffsll(m) - 1;
            m &= m - 1;
            u64 wv = swtab[(n << 7) + tx];       // (lx, gy) — bank idx n-indep
            u64 hv = shtab[(r << 6) + n];        // (gx, ly)
            u64 t  = pmul(wv, hv);               // (lx*gx, gy*ly)
            float t0, t1; upk(t0, t1, t);
            float xy = fmaxf(t0, t1);
            u64 xyp = pk(xy, xy);
            ulonglong2 ca = sclsA[n];
            ulonglong2 cb = sclsB[n];
            float p0, p1;
            upk(p0, p1, pmul(xyp, ca.x)); a0 = fmaxf(a0, p0); a1 = fmaxf(a1, p1);
            upk(p0, p1, pmul(xyp, ca.y)); a2 = fmaxf(a2, p0); a3 = fmaxf(a3, p1);
            upk(p0, p1, pmul(xyp, cb.x)); a4 = fmaxf(a4, p0); a5 = fmaxf(a5, p1);
            upk(p0, p1, pmul(xyp, cb.y)); a6 = fmaxf(a6, p0); a7 = fmaxf(a7, p1);
        }

        float* o = out + (((size_t)b * NCLS) * Hd + h) * Wd + tx;
        const int cs = Hd * Wd;
        o[0 * cs] = a0; o[1 * cs] = a1; o[2 * cs] = a2; o[3 * cs] = a3;
        o[4 * cs] = a4; o[5 * cs] = a5; o[6 * cs] = a6; o[7 * cs] = a7;
    }
}

extern "C" void kernel_launch(void* const* d_in, const int* in_sizes, int n_in,
                              void* d_out, int out_size)
{
    const float* in = (const float*)d_in[0];
    float* out = (float*)d_out;
    int B = in_sizes[0] / (INCH * NUMB);

    size_t dynsmem = (size_t)(NUMB * Wd + RPB * NUMB + 2 * Wd + 2 * RPB) * sizeof(u64);
    cudaFuncSetAttribute(layout_bbox_kernel,
                         cudaFuncAttributeMaxDynamicSharedMemorySize,
                         (int)dynsmem);

    dim3 grid(Hd / RPB, B);   // (8, B)
    dim3 block(Wd, TY);       // 128 x 8
    layout_bbox_kernel<<<grid, block, dynsmem>>>(in, out);
}

// round 4
// speedup vs baseline: 1.3948x; 1.1095x over previous
#include <cuda_runtime.h>
#include <stdint.h>

// LayoutBBox: in (B,12,64) f32 -> out (B,8,128,128) f32
// out[b,c,h,w] = max_n xy[n,h,w]*cls[n,c], xy = max(lx(w)*gx(h), ly(h)*gy(w))
// Kernel 1 (prep): per-(b,w)/(b,h) exact nonzero bitmasks + packed box records.
// Kernel 2 (main): smem-free, sync-free; visits only exact nonzero boxes.

constexpr int Wd   = 128;
constexpr int Hd   = 128;
constexpr int NUMB = 64;
constexpr int NCLS = 8;
constexpr int INCH = 12;
constexpr int MAXB = 16;

using u64 = unsigned long long;

__device__ __forceinline__ u64 pk(float lo, float hi) {
    u64 r; asm("mov.b64 %0,{%1,%2};" : "=l"(r) : "f"(lo), "f"(hi)); return r;
}
__device__ __forceinline__ void upk(float& lo, float& hi, u64 v) {
    asm("mov.b64 {%0,%1},%2;" : "=f"(lo), "=f"(hi) : "l"(v));
}
__device__ __forceinline__ u64 pmul(u64 a, u64 b) {
    u64 r; asm("mul.rn.f32x2 %0,%1,%2;" : "=l"(r) : "l"(a), "l"(b)); return r;
}

struct __align__(16) Rec {              // 48 B per box
    float4     p;                       // x1, x2, y1, y2
    ulonglong2 ca;                      // packed (c0,c1),(c2,c3)
    ulonglong2 cb;                      // packed (c4,c5),(c6,c7)
};

__device__ ulonglong2 g_cmask[MAXB][Wd];   // (Mlx, Mgw) per (b,w)
__device__ ulonglong2 g_rmask[MAXB][Hd];   // (Mgh, Mly) per (b,h)
__device__ Rec        g_rec[MAXB][NUMB];

// ---------------- prep kernel: grid (2, B), block 1024 ----------------
__global__ void prep_kernel(const float* __restrict__ in)
{
    const int b   = blockIdx.y;
    const int tid = threadIdx.x;
    const float* base = in + (size_t)b * INCH * NUMB;

    if (blockIdx.x == 0) {
        // box records (threads 0..63)
        if (tid < NUMB) {
            float xc = base[0 * NUMB + tid] * 128.0f;
            float yc = base[1 * NUMB + tid] * 128.0f;
            float bw = base[2 * NUMB + tid] * 128.0f;
            float bh = base[3 * NUMB + tid] * 128.0f;
            Rec r;
            r.p = make_float4(xc - 0.5f * bw, xc + 0.5f * bw,
                              yc - 0.5f * bh, yc + 0.5f * bh);
            r.ca.x = pk(base[4 * NUMB + tid],  base[5 * NUMB + tid]);
            r.ca.y = pk(base[6 * NUMB + tid],  base[7 * NUMB + tid]);
            r.cb.x = pk(base[8 * NUMB + tid],  base[9 * NUMB + tid]);
            r.cb.y = pk(base[10 * NUMB + tid], base[11 * NUMB + tid]);
            g_rec[b][tid] = r;
        }
        // column masks, byte-parallel: w = tid>>3, byte j = tid&7
        {
            int w = tid >> 3, j = tid & 7;
            float wf = (float)w;
            unsigned blx = 0, bgw = 0;
            #pragma unroll
            for (int k = 0; k < 8; k++) {
                int n = 8 * j + k;
                float xc = base[0 * NUMB + n] * 128.0f;
                float bw = base[2 * NUMB + n] * 128.0f;
                float x1 = xc - 0.5f * bw, x2 = xc + 0.5f * bw;
                if (fabsf(wf - x1) < 1.0f || fabsf(x2 - wf) < 1.0f) blx |= 1u << k;
                if (wf > x1 && wf < x2)                             bgw |= 1u << k;
            }
            unsigned char* dst = (unsigned char*)&g_cmask[b][w];
            dst[j]     = (unsigned char)blx;   // Mlx byte
            dst[8 + j] = (unsigned char)bgw;   // Mgw byte
        }
    } else {
        // row masks
        int h = tid >> 3, j = tid & 7;
        float hf = (float)h;
        unsigned bgh = 0, bly = 0;
        #pragma unroll
        for (int k = 0; k < 8; k++) {
            int n = 8 * j + k;
            float yc = base[1 * NUMB + n] * 128.0f;
            float bh = base[3 * NUMB + n] * 128.0f;
            float y1 = yc - 0.5f * bh, y2 = yc + 0.5f * bh;
            if (hf > y1 && hf < y2)                             bgh |= 1u << k;
            if (fabsf(hf - y1) < 1.0f || fabsf(y2 - hf) < 1.0f) bly |= 1u << k;
        }
        unsigned char* dst = (unsigned char*)&g_rmask[b][h];
        dst[j]     = (unsigned char)bgh;   // Mgh byte
        dst[8 + j] = (unsigned char)bly;   // Mly byte
    }
}

// ---------------- main kernel: grid (Hd/2, B), block (128, 2) ----------------
__global__ __launch_bounds__(256)
void layout_bbox_main(float* __restrict__ out)
{
    const int tx = threadIdx.x;                    // w
    const int b  = blockIdx.y;
    const int h  = blockIdx.x * 2 + threadIdx.y;
    const float wf = (float)tx;
    const float hf = (float)h;

    const ulonglong2 cm = g_cmask[b][tx];
    const ulonglong2 rm = g_rmask[b][h];
    u64 m = (cm.x & rm.x) | (cm.y & rm.y);         // exact nonzero-box set

    float a0 = 0.f, a1 = 0.f, a2 = 0.f, a3 = 0.f;
    float a4 = 0.f, a5 = 0.f, a6 = 0.f, a7 = 0.f;

    while (m) {
        int n = __ffsll((long long)m) - 1;
        m &= m - 1;
        Rec r = g_rec[b][n];                       // 3x LDG.128, L1-resident

        float dx1 = wf - r.p.x, dx2 = r.p.y - wf;
        float dy1 = hf - r.p.z, dy2 = r.p.w - hf;
        float lx = fmaxf(0.0f, fmaxf(1.0f - fabsf(dx1), 1.0f - fabsf(dx2)));
        float gy = __saturatef(dx1) * __saturatef(dx2);
        float gx = __saturatef(dy1) * __saturatef(dy2);
        float ly = fmaxf(0.0f, fmaxf(1.0f - fabsf(dy1), 1.0f - fabsf(dy2)));
        float xy = fmaxf(lx * gx, ly * gy);

        u64 xyp = pk(xy, xy);
        float p0, p1;
        upk(p0, p1, pmul(xyp, r.ca.x)); a0 = fmaxf(a0, p0); a1 = fmaxf(a1, p1);
        upk(p0, p1, pmul(xyp, r.ca.y)); a2 = fmaxf(a2, p0); a3 = fmaxf(a3, p1);
        upk(p0, p1, pmul(xyp, r.cb.x)); a4 = fmaxf(a4, p0); a5 = fmaxf(a5, p1);
        upk(p0, p1, pmul(xyp, r.cb.y)); a6 = fmaxf(a6, p0); a7 = fmaxf(a7, p1);
    }

    float* o = out + (((size_t)b * NCLS) * Hd + h) * Wd + tx;
    const int cs = Hd * Wd;
    o[0 * cs] = a0; o[1 * cs] = a1; o[2 * cs] = a2; o[3 * cs] = a3;
    o[4 * cs] = a4; o[5 * cs] = a5; o[6 * cs] = a6; o[7 * cs] = a7;
}

extern "C" void kernel_launch(void* const* d_in, const int* in_sizes, int n_in,
                              void* d_out, int out_size)
{
    const float* in = (const float*)d_in[0];
    float* out = (float*)d_out;
    int B = in_sizes[0] / (INCH * NUMB);   // 16

    prep_kernel<<<dim3(2, B), 1024>>>(in);
    layout_bbox_main<<<dim3(Hd / 2, B), dim3(128, 2)>>>(out);
}